// round 17
// baseline (speedup 1.0000x reference)
#include <cuda_runtime.h>
#include <cuda_fp16.h>
#include <cstdint>

#define NTOT 16384
#define KN   16
#define NP   15
#define CIN  64
#define COUT 128
#define KTOT (NP * CIN)        // 960

// ---------------- global scratch ----------------
__device__ __half g_B[COUT * KTOT];             // [cout][k], fp16 (= W^T)
__device__ __half g_F[(size_t)NTOT * CIN];      // features fp16
__device__ int    g_cnt;

typedef unsigned long long u64;
typedef unsigned int u32;

__device__ __forceinline__ u32 h2pk(float a, float b) {
    __half ha = __float2half_rn(a), hb = __float2half_rn(b);
    unsigned short ua = *reinterpret_cast<unsigned short*>(&ha);
    unsigned short ub = *reinterpret_cast<unsigned short*>(&hb);
    return (u32)ua | ((u32)ub << 16);
}
__device__ __forceinline__ u32 smem_u32(const void* p) {
    u32 a; asm("{ .reg .u64 t; cvta.to.shared.u64 t, %1; cvt.u32.u64 %0, t; }"
               : "=r"(a) : "l"(p));
    return a;
}
__device__ __forceinline__ void ldmx4(u32* r, u32 addr) {
    asm volatile("ldmatrix.sync.aligned.m8n8.x4.shared.b16 {%0,%1,%2,%3}, [%4];"
                 : "=r"(r[0]), "=r"(r[1]), "=r"(r[2]), "=r"(r[3]) : "r"(addr));
}
__device__ __forceinline__ void ldmx4t(u32* r, u32 addr) {
    asm volatile("ldmatrix.sync.aligned.m8n8.x4.trans.shared.b16 {%0,%1,%2,%3}, [%4];"
                 : "=r"(r[0]), "=r"(r[1]), "=r"(r[2]), "=r"(r[3]) : "r"(addr));
}
__device__ __forceinline__ void mma_f16(float* d, const u32* a, const u32* b) {
    asm volatile("mma.sync.aligned.m16n8k16.row.col.f32.f16.f16.f32 "
                 "{%0,%1,%2,%3}, {%4,%5,%6,%7}, {%8,%9}, {%0,%1,%2,%3};"
                 : "+f"(d[0]), "+f"(d[1]), "+f"(d[2]), "+f"(d[3])
                 : "r"(a[0]), "r"(a[1]), "r"(a[2]), "r"(a[3]),
                   "r"(b[0]), "r"(b[1]));
}
__device__ __forceinline__ void cpa16(u32 dst, const void* src) {
    asm volatile("cp.async.cg.shared.global [%0], [%1], 16;"
                 :: "r"(dst), "l"(src) : "memory");
}

// ====== fused kernel: grid 512, 256 threads, QB=32, 2 CTAs/SM ======
#define NT 256
#define QB 32
#define SBQ 8                  // queries per sub-batch
#define NSB 4
#define OFF_A    0             // 15 chunks x (32 rows x 128B, XOR swz), stride 4112
#define ACH      4112
#define OFF_R    61696         // region 48KB: A: fbuf 2x16KB + infl 2x4KB | B: ring 3x16KB
#define FBUF     16384
#define IBUF     4096
#define OFF_KP   110848
#define OFF_Q    111040
#define OFF_NIDX 111424        // 2048 -> 113472
#define SMEM_TOT 113664

#define NCHUNK 15
#define BTILE  16384

__global__ __launch_bounds__(NT, 2)
void kpconv_fused(const float* __restrict__ query,
                  const float* __restrict__ support,
                  const int*   __restrict__ nidx,
                  const float* __restrict__ feats,
                  const float* __restrict__ kp,
                  const float* __restrict__ W,
                  float* __restrict__ out)
{
    extern __shared__ char sm[];
    const u32 sb = smem_u32(sm);
    float* s_kp   = (float*)(sm + OFF_KP);
    float* s_q    = (float*)(sm + OFF_Q);
    int*   s_nidx = (int*)(sm + OFF_NIDX);

    const int tid = threadIdx.x;
    const int bid = blockIdx.x;
    const int m0  = bid * QB;

    // ---- step 0a: W -> g_B fp16, CTAs 0..119 ----
    if (bid < 120) {
        int idx4 = bid * NT + tid;
        int n  = idx4 / 240;
        int kq = idx4 - n * 240;
        int k  = kq * 4;
        int p  = k >> 6, cin = k & 63;
        const float* wp = W + p * CIN * COUT + cin * COUT + n;
        float w0 = __ldg(wp);
        float w1 = __ldg(wp + COUT);
        float w2 = __ldg(wp + 2 * COUT);
        float w3 = __ldg(wp + 3 * COUT);
        uint2 vh = make_uint2(h2pk(w0, w1), h2pk(w2, w3));
        *(uint2*)(g_B + (size_t)n * KTOT + k) = vh;
    }
    // ---- step 0b: feats -> g_F fp16, CTAs 0..255 ----
    if (bid < 256) {
        const float* fsrc = feats + (size_t)bid * 64 * CIN;
        __half*      fdst = g_F   + (size_t)bid * 64 * CIN;
        #pragma unroll
        for (int t = 0; t < 4; t++) {
            int idx = tid + t * NT;
            uint4 v = __ldg((const uint4*)fsrc + idx);
            uint2 h = make_uint2(h2pk(__uint_as_float(v.x), __uint_as_float(v.y)),
                                 h2pk(__uint_as_float(v.z), __uint_as_float(v.w)));
            *(uint2*)(fdst + idx * 4) = h;
        }
        __threadfence();
        __syncthreads();
        if (tid == 0) atomicAdd(&g_cnt, 1);
    }

    // ---- metadata ----
    for (int i = tid; i < QB * KN; i += NT) s_nidx[i] = nidx[m0 * KN + i];
    if (tid < NP * 3)  s_kp[tid] = kp[tid];
    if (tid < QB * 3)  s_q[tid]  = query[m0 * 3 + tid];

    // ---- wait for g_F / g_B via acquire loads ----
    if (tid == 0) {
        int v;
        do {
            asm volatile("ld.global.acquire.gpu.b32 %0, [%1];"
                         : "=r"(v) : "l"(&g_cnt) : "memory");
        } while (v < 256);
    }
    __syncthreads();
    __threadfence();

    const int wid  = tid >> 5;
    const int lane = tid & 31;
    const int c0   = bid % NCHUNK;  // per-CTA B-chunk stagger

    // frag addressing constants (verified)
    const int aprow = (lane & 7) + ((lane >> 3) & 1) * 8;
    const u32 abh   = (u32)(((lane >> 4) & 1) * 16);
    const int mgrp  = lane >> 3;
    const int krow  = (mgrp & 1) * 8 + (lane & 7);
    const u32 cbyte0 = (u32)((mgrp >> 1) * 16);

    // B-load helper (ring slot i%3, chunk (c0+i)%15) — used in A-tail & phase B
    auto issueB = [&](int i) {
        int cc = c0 + i; if (cc >= NCHUNK) cc -= NCHUNK;
        u32 dstb = sb + OFF_R + (u32)(i % 3) * BTILE;
        #pragma unroll
        for (int j = 0; j < 4; j++) {
            int idx = tid + j * NT;
            int row = idx >> 3, c16 = idx & 7;
            u32 dst = dstb + (u32)(row * 128 + ((c16 * 16) ^ ((row & 7) * 16)));
            cpa16(dst, g_B + (size_t)row * KTOT + cc * 64 + c16 * 8);
        }
        asm volatile("cp.async.commit_group;" ::: "memory");
    };

    // gather helper: sub-batch s (128 rows) into fbuf (s&1)
    auto issueG = [&](int s) {
        u32 dstb = sb + OFF_R + (u32)(s & 1) * FBUF;
        #pragma unroll
        for (int j = 0; j < 4; j++) {
            int idx = tid + j * NT;           // 0..1023
            int row = idx >> 3;               // 0..127
            int c16 = idx & 7;
            int m   = s_nidx[s * 128 + row];
            u32 dst = dstb + (u32)(row * 128)
                    + (((u32)(c16 * 16)) ^ ((u32)(row & 7) * 16));
            cpa16(dst, g_F + (size_t)m * CIN + c16 * 8);
        }
        asm volatile("cp.async.commit_group;" ::: "memory");
    };

    // =================== phase A: pipelined aggregation ===============
    issueG(0);

    #pragma unroll
    for (int s = 0; s < NSB; s++) {
        // prefetch next gather (its buffer was freed at end-sync of s-1)
        if (s + 1 < NSB) issueG(s + 1);
        else             issueB(0);   // A-tail: ring slot0 (=fbuf0) free after s=2

        // influences for sub-batch s: 2 threads per (q,k) pair
        {
            int pair = tid >> 1;          // 0..127
            int half = tid & 1;
            int qq = pair >> 4;           // 0..7
            int kk = pair & 15;
            int m  = s_nidx[s * 128 + pair];
            int qg = s * SBQ + qq;
            float rx = support[m * 3 + 0] - s_q[qg * 3 + 0];
            float ry = support[m * 3 + 1] - s_q[qg * 3 + 1];
            float rz = support[m * 3 + 2] - s_q[qg * 3 + 2];
            __half* ib = (__half*)(sm + OFF_R + 2 * FBUF + (s & 1) * IBUF)
                         + qq * 256 + kk;
            int p0 = half * 8;
            int p1 = half ? NP : 8;
            #pragma unroll
            for (int p = p0; p < p1; p++) {
                float dx = rx - s_kp[p * 3 + 0];
                float dy = ry - s_kp[p * 3 + 1];
                float dz = rz - s_kp[p * 3 + 2];
                float d  = sqrtf(fmaf(dx, dx, fmaf(dy, dy, dz * dz)));
                ib[p * 16] = __float2half_rn(fmaxf(1.0f - d, 0.0f));
            }
            if (half) ib[15 * 16] = __half(0.0f);
        }
        asm volatile("cp.async.wait_group 1;" ::: "memory");  // gather(s) done
        __syncthreads();

        // mma aggregation: 1 query per warp
        {
            const int q  = wid;               // 0..7 local
            const int Lq = s * SBQ + q;       // 0..31 row in s_A chunks

            u32 a[4];
            ldmx4(a, sb + OFF_R + 2 * FBUF + (u32)((s & 1) * IBUF)
                     + (u32)(q * 512 + aprow * 32) + abh);

            const u32 fbase = sb + OFF_R + (u32)((s & 1) * FBUF)
                            + (u32)((q * 16 + krow) * 128);
            const u32 fswz  = (u32)((krow & 7) * 16);
            const int prow = lane >> 2;
            const int c4   = lane & 3;
            const u32 swzL = (u32)((Lq & 7) * 16);

            #pragma unroll
            for (int cc = 0; cc < 4; cc++) {
                u32 b[4];
                ldmx4t(b, fbase + (((u32)(cc * 32) + cbyte0) ^ fswz));
                float acc[2][4];
                #pragma unroll
                for (int h = 0; h < 2; h++)
                    #pragma unroll
                    for (int e = 0; e < 4; e++) acc[h][e] = 0.0f;
                mma_f16(acc[0], a, &b[0]);
                mma_f16(acc[1], a, &b[2]);

                #pragma unroll
                for (int h = 0; h < 2; h++) {
                    u32 lo = h2pk(acc[h][0], acc[h][1]);
                    u32 hi = h2pk(acc[h][2], acc[h][3]);
                    u32 x  = (u32)((2 * cc + h) * 16);
                    u32 off = (u32)(Lq * 128) + (x ^ swzL) + (u32)(c4 * 4);
                    *(u32*)(sm + OFF_A + prow * ACH + off) = lo;
                    if (prow != 7)
                        *(u32*)(sm + OFF_A + (prow + 8) * ACH + off) = hi;
                }
            }
        }
        __syncthreads();   // fbuf[s&1] consumed; safe for reuse at s+2
    }

    // =================== phase B: GEMM out[32x128] = s_A @ B^T ================
    const int wm = wid >> 2;
    const int wn = wid & 3;

    const int a_row  = wm * 16 + aprow;
    const u32 a_mask = (u32)((a_row & 7) * 16);
    const int b_row  = wn * 32 + (lane & 7) + ((lane >> 4) & 1) * 8;
    const int b_bh   = ((lane >> 3) & 1) * 16;
    const u32 b_mask = (u32)((b_row & 7) * 16);

    float acc[4][4];
    #pragma unroll
    for (int ni = 0; ni < 4; ni++)
        #pragma unroll
        for (int e = 0; e < 4; e++) acc[ni][e] = 0.0f;

    issueB(1);   // B(0) already issued in A-tail

    for (int i = 0; i < NCHUNK; i++) {
        if (i < NCHUNK - 1) {
            asm volatile("cp.async.wait_group 1;" ::: "memory");
        } else {
            asm volatile("cp.async.wait_group 0;" ::: "memory");
        }
        __syncthreads();            // chunk i published; chunk i-1 consumed
        if (i + 2 < NCHUNK) issueB(i + 2);

        int cc = c0 + i; if (cc >= NCHUNK) cc -= NCHUNK;
        const u32 aBase = sb + OFF_A + (u32)cc * ACH + (u32)(a_row * 128);
        const u32 bBase = sb + OFF_R + (u32)(i % 3) * BTILE + (u32)(b_row * 128);

        #pragma unroll
        for (int ks = 0; ks < 4; ks++) {
            const u32 aOff = ((u32)(ks * 32) + abh) ^ a_mask;
            const u32 bOff = (u32)((ks * 32 + b_bh)) ^ b_mask;

            u32 b[8];
            #pragma unroll
            for (int nj = 0; nj < 2; nj++)
                ldmx4(&b[nj * 4], bBase + (u32)(nj * 16 * 128) + bOff);

            u32 a[4];
            ldmx4(a, aBase + aOff);
            #pragma unroll
            for (int ni = 0; ni < 4; ni++)
                mma_f16(acc[ni], a, &b[(ni >> 1) * 4 + (ni & 1) * 2]);
        }
    }

    // ---- epilogue ----
    {
        int row = m0 + wm * 16 + (lane >> 2);
        #pragma unroll
        for (int ni = 0; ni < 4; ni++) {
            int col = wn * 32 + ni * 8 + (lane & 3) * 2;
            *(float2*)(out + (size_t)row * COUT + col) =
                make_float2(acc[ni][0], acc[ni][1]);
            *(float2*)(out + (size_t)(row + 8) * COUT + col) =
                make_float2(acc[ni][2], acc[ni][3]);
        }
    }
}

// ================= launch =================
extern "C" void kernel_launch(void* const* d_in, const int* in_sizes, int n_in,
                              void* d_out, int out_size) {
    const float* query   = (const float*)d_in[0];
    const float* support = (const float*)d_in[1];
    const int*   nidx    = (const int*)d_in[2];
    const float* feats   = (const float*)d_in[3];
    const float* W       = (const float*)d_in[4];
    const float* kp      = (const float*)d_in[5];
    float* out = (float*)d_out;

    cudaFuncSetAttribute(kpconv_fused,
                         cudaFuncAttributeMaxDynamicSharedMemorySize, SMEM_TOT);
    kpconv_fused<<<NTOT / QB, NT, SMEM_TOT>>>(
        query, support, nidx, feats, kp, W, out);
}